// round 4
// baseline (speedup 1.0000x reference)
#include <cuda_runtime.h>
#include <cstdint>

// Chamfer distance, B=4,S=4 pairs, N=M=4096 Gaussian 3D points.
// Grid-accelerated exact NN:
//  1) build_cells: counting-sort each of the 32 point lists into a 64x64
//     (x,y) cell grid over [-5,5]^2 (edge cells catch outliers; their
//     nominal bounds are +-inf so pruning stays exact). Sorted float4 +
//     u16 cell offsets go to __device__ scratch.
//  2) chamfer_query: per block, stage one sorted target list (64KB) +
//     offsets (8KB) into smem; each thread finds the exact NN of one query
//     via expanding Chebyshev rings with exact per-cell distance bounds.
//     Ring r terminates when ((r-1)*w)^2 >= best. Block-reduced means
//     accumulate into out[S,B] (zeroed by a memset node).

#define BDIM 4
#define SDIM 4
#define NPAIRS 16
#define NBX 64
#define NBY 64
#define NCELL (NBX * NBY)
#define MAXPTS 4096
#define GRIDMIN (-5.0f)
#define GRIDW 0.15625f /* 10/64 */
#define INVW 6.4f
#define QTHREADS 512

__device__ float4 g_sorted[2 * NPAIRS][MAXPTS];
__device__ unsigned short g_cellStart[2 * NPAIRS][NCELL + 1];

// ---------------- counting sort into cells ----------------
__global__ void build_cells(const float* __restrict__ outp,
                            const float* __restrict__ tgtp,
                            int Nq, int Mt) {
    const int list = blockIdx.x;             // 0..31
    const int set = list >> 4, pair = list & 15;
    const float* pts = set ? tgtp : outp;
    const int n = set ? Mt : Nq;
    const float* base = pts + (size_t)pair * n * 3;

    __shared__ int cnt[NCELL];
    __shared__ int partial[256];
    const int t = threadIdx.x;

    for (int c = t; c < NCELL; c += 256) cnt[c] = 0;
    __syncthreads();

    // histogram
    for (int i = t; i < n; i += 256) {
        float x = base[3 * i], y = base[3 * i + 1];
        int cx = min(max(__float2int_rd((x - GRIDMIN) * INVW), 0), NBX - 1);
        int cy = min(max(__float2int_rd((y - GRIDMIN) * INVW), 0), NBY - 1);
        atomicAdd(&cnt[cy * NBX + cx], 1);
    }
    __syncthreads();

    // exclusive prefix sum over NCELL (16 cells per thread)
    int csum = 0;
#pragma unroll
    for (int j = 0; j < 16; j++) csum += cnt[t * 16 + j];
    partial[t] = csum;
    __syncthreads();
    for (int off = 1; off < 256; off <<= 1) {
        int v = (t >= off) ? partial[t - off] : 0;
        __syncthreads();
        partial[t] += v;
        __syncthreads();
    }
    int run = (t == 0) ? 0 : partial[t - 1];
#pragma unroll
    for (int j = 0; j < 16; j++) {
        int c = t * 16 + j;
        int v = cnt[c];
        cnt[c] = run;   // exclusive start
        run += v;
    }
    __syncthreads();

    // publish cell starts BEFORE scatter mutates cnt
    for (int c = t; c < NCELL; c += 256)
        g_cellStart[list][c] = (unsigned short)cnt[c];
    if (t == 0) g_cellStart[list][NCELL] = (unsigned short)n;
    __syncthreads();

    // scatter
    for (int i = t; i < n; i += 256) {
        float x = base[3 * i], y = base[3 * i + 1], z = base[3 * i + 2];
        int cx = min(max(__float2int_rd((x - GRIDMIN) * INVW), 0), NBX - 1);
        int cy = min(max(__float2int_rd((y - GRIDMIN) * INVW), 0), NBY - 1);
        int idx = atomicAdd(&cnt[cy * NBX + cx], 1);
        g_sorted[list][idx] = make_float4(x, y, z, 0.f);
    }
}

// ---------------- query ----------------
__device__ __forceinline__ void scan_cell(int cx, int cy,
                                          float qx, float qy, float qz,
                                          const float4* __restrict__ spts,
                                          const unsigned short* __restrict__ sstart,
                                          float& best) {
    // exact (padded) cell bounds; edge cells extend to +-inf
    float xmin = (cx == 0)       ? -1e30f : GRIDMIN + cx * GRIDW - 1e-4f;
    float xmax = (cx == NBX - 1) ?  1e30f : GRIDMIN + (cx + 1) * GRIDW + 1e-4f;
    float ymin = (cy == 0)       ? -1e30f : GRIDMIN + cy * GRIDW - 1e-4f;
    float ymax = (cy == NBY - 1) ?  1e30f : GRIDMIN + (cy + 1) * GRIDW + 1e-4f;
    float dx = fmaxf(fmaxf(xmin - qx, qx - xmax), 0.f);
    float dy = fmaxf(fmaxf(ymin - qy, qy - ymax), 0.f);
    if (fmaf(dx, dx, dy * dy) >= best) return;
    int c = cy * NBX + cx;
    int j1 = sstart[c + 1];
    for (int j = sstart[c]; j < j1; j++) {
        float4 p = spts[j];
        float ax = p.x - qx, ay = p.y - qy, az = p.z - qz;
        float d2 = fmaf(az, az, fmaf(ay, ay, ax * ax));
        best = fminf(best, d2);
    }
}

extern __shared__ char smraw[];

__global__ __launch_bounds__(QTHREADS)
void chamfer_query(const float* __restrict__ outp,
                   const float* __restrict__ tgtp,
                   int Nq, int Mt, float* __restrict__ out) {
    const int dir = blockIdx.z;      // 0: out->tgt, 1: tgt->out
    const int pair = blockIdx.y;
    const float* qpts = dir ? tgtp : outp;
    const int nq = dir ? Mt : Nq;
    const int tlist = (dir ? 0 : 1) * NPAIRS + pair;  // the OTHER set
    const int tn = dir ? Nq : Mt;

    float4* spts = (float4*)smraw;
    unsigned short* sstart = (unsigned short*)(smraw + sizeof(float4) * MAXPTS);

    for (int i = threadIdx.x; i < tn; i += QTHREADS)
        spts[i] = g_sorted[tlist][i];
    for (int c = threadIdx.x; c <= NCELL; c += QTHREADS)
        sstart[c] = g_cellStart[tlist][c];
    __syncthreads();

    const int qi = blockIdx.x * QTHREADS + threadIdx.x;
    float lsum = 0.f;
    if (qi < nq) {
        const float* qb = qpts + (size_t)pair * nq * 3 + (size_t)qi * 3;
        float qx = qb[0], qy = qb[1], qz = qb[2];
        int qcx = min(max(__float2int_rd((qx - GRIDMIN) * INVW), 0), NBX - 1);
        int qcy = min(max(__float2int_rd((qy - GRIDMIN) * INVW), 0), NBY - 1);
        float best = 1e30f;

        for (int r = 0; r < NBX; r++) {
            if (r >= 2) {
                float dr = (float)(r - 1) * GRIDW - 1e-4f;
                if (dr * dr >= best) break;
            }
            int x0 = qcx - r, x1 = qcx + r;
            int y0 = qcy - r, y1 = qcy + r;
            int cya = max(y0, 0), cyb = min(y1, NBY - 1);
            for (int cy = cya; cy <= cyb; cy++) {
                if (cy == y0 || cy == y1) {
                    int cxa = max(x0, 0), cxb = min(x1, NBX - 1);
                    for (int cx = cxa; cx <= cxb; cx++)
                        scan_cell(cx, cy, qx, qy, qz, spts, sstart, best);
                } else {
                    if (x0 >= 0)  scan_cell(x0, cy, qx, qy, qz, spts, sstart, best);
                    if (x1 < NBX) scan_cell(x1, cy, qx, qy, qz, spts, sstart, best);
                }
            }
        }
        lsum = best;  // diff-form d2 >= 0, matches clamped reference
    }

    // block reduce + one atomicAdd
#pragma unroll
    for (int off = 16; off; off >>= 1)
        lsum += __shfl_down_sync(0xffffffffu, lsum, off);
    __shared__ float red[QTHREADS / 32];
    const int wid = threadIdx.x >> 5;
    if ((threadIdx.x & 31) == 0) red[wid] = lsum;
    __syncthreads();
    if (threadIdx.x == 0) {
        float tot = 0.f;
#pragma unroll
        for (int w = 0; w < QTHREADS / 32; w++) tot += red[w];
        int b = pair / SDIM;
        int s = pair % SDIM;
        atomicAdd(out + s * BDIM + b, tot / (float)nq);
    }
}

extern "C" void kernel_launch(void* const* d_in, const int* in_sizes, int n_in,
                              void* d_out, int out_size) {
    const float* outp = (const float*)d_in[0];  // [B,S,N,3]
    const float* tgtp = (const float*)d_in[1];  // [B,S,M,3]
    float* out = (float*)d_out;                  // [S,B]

    const int Nq = in_sizes[0] / (NPAIRS * 3);
    const int Mt = in_sizes[1] / (NPAIRS * 3);

    cudaMemsetAsync(out, 0, (size_t)out_size * sizeof(float));

    build_cells<<<2 * NPAIRS, 256>>>(outp, tgtp, Nq, Mt);

    const size_t smem = sizeof(float4) * MAXPTS +
                        sizeof(unsigned short) * (NCELL + 1);
    cudaFuncSetAttribute(chamfer_query,
                         cudaFuncAttributeMaxDynamicSharedMemorySize, (int)smem);

    const int maxq = Nq > Mt ? Nq : Mt;
    dim3 grid((maxq + QTHREADS - 1) / QTHREADS, NPAIRS, 2);
    chamfer_query<<<grid, QTHREADS, smem>>>(outp, tgtp, Nq, Mt, out);
}

// round 5
// speedup vs baseline: 1.5739x; 1.5739x over previous
#include <cuda_runtime.h>
#include <cstdint>

// Chamfer distance, B=4,S=4 pairs, N=M=4096 Gaussian 3D points.
// 1-D sorted-scan exact NN:
//  1) build_sorted: counting-sort each of the 32 lists by x into 256 bins
//     over [-5,5] (edge bins absorb outliers). Sorted float4 + u16 bin
//     starts in __device__ scratch.
//  2) chamfer_query: block stages the sorted target list as SoA
//     (x,y,z,h=0.5*|t|^2) in smem. Each thread takes one SORTED query,
//     scans the contiguous target range of bins [qb-3, qb+4) with packed
//     fma.rn.f32x2 (2 evals / 3 FFMA2, mins on ALU pipe), then expands
//     bin-by-bin until both bin-edge bounds certify the min is exact.

#define BDIM 4
#define SDIM 4
#define NPAIRS 16
#define NB 256
#define MAXPTS 4096
#define TSP (MAXPTS + 8)          // padded, even, sentinels at tail
#define GRIDMIN (-5.0f)
#define BW 0.0390625f             /* 10/256 */
#define INVBW 25.6f
#define QTHREADS 256

__device__ float4 g_sorted[2 * NPAIRS][MAXPTS];
__device__ unsigned short g_start[2 * NPAIRS][NB + 1];

__device__ __forceinline__ uint64_t fma2(uint64_t a, uint64_t b, uint64_t c) {
    uint64_t d;
    asm("fma.rn.f32x2 %0, %1, %2, %3;" : "=l"(d) : "l"(a), "l"(b), "l"(c));
    return d;
}
__device__ __forceinline__ uint64_t pack2(float lo, float hi) {
    uint64_t d;
    asm("mov.b64 %0, {%1, %2};" : "=l"(d) : "f"(lo), "f"(hi));
    return d;
}
__device__ __forceinline__ void unpack2(uint64_t v, float& lo, float& hi) {
    asm("mov.b64 {%0, %1}, %2;" : "=f"(lo), "=f"(hi) : "l"(v));
}

// ---------------- counting sort by x into 256 bins ----------------
__global__ void build_sorted(const float* __restrict__ outp,
                             const float* __restrict__ tgtp,
                             int Nq, int Mt) {
    const int list = blockIdx.x;            // 0..31
    const int set = list >> 4, pair = list & 15;
    const float* pts = set ? tgtp : outp;
    const int n = set ? Mt : Nq;
    const float* base = pts + (size_t)pair * n * 3;

    __shared__ int cnt[NB];
    const int t = threadIdx.x;              // 256 threads

    cnt[t] = 0;
    __syncthreads();

    for (int i = t; i < n; i += NB) {
        float x = base[3 * i];
        int b = min(max(__float2int_rd((x - GRIDMIN) * INVBW), 0), NB - 1);
        atomicAdd(&cnt[b], 1);
    }
    __syncthreads();

    // inclusive Hillis-Steele scan over 256 bins
    int v = cnt[t];
    __syncthreads();
#pragma unroll
    for (int off = 1; off < NB; off <<= 1) {
        int u = (t >= off) ? cnt[t - off] : 0;
        __syncthreads();
        cnt[t] += u;
        __syncthreads();
    }
    int start = cnt[t] - v;  // exclusive

    g_start[list][t] = (unsigned short)start;
    if (t == 0) g_start[list][NB] = (unsigned short)n;

    // reuse cnt as running offsets
    __syncthreads();
    cnt[t] = start;
    __syncthreads();

    for (int i = t; i < n; i += NB) {
        float x = base[3 * i], y = base[3 * i + 1], z = base[3 * i + 2];
        int b = min(max(__float2int_rd((x - GRIDMIN) * INVBW), 0), NB - 1);
        int idx = atomicAdd(&cnt[b], 1);
        g_sorted[list][idx] = make_float4(x, y, z, 0.f);
    }
}

// ---------------- query ----------------
extern __shared__ float s_mem[];

__device__ __forceinline__ void scan_range(
    int a, int b,  // even point indices
    uint64_t nx, uint64_t ny, uint64_t nz,
    const uint64_t* __restrict__ px, const uint64_t* __restrict__ py,
    const uint64_t* __restrict__ pz, const uint64_t* __restrict__ ph,
    float& mlo, float& mhi) {
    const int j0 = a >> 1, j1 = b >> 1;
#pragma unroll 4
    for (int j = j0; j < j1; j++) {
        uint64_t t = fma2(nx, px[j], ph[j]);
        t = fma2(ny, py[j], t);
        t = fma2(nz, pz[j], t);
        float lo, hi;
        unpack2(t, lo, hi);
        mlo = fminf(mlo, lo);
        mhi = fminf(mhi, hi);
    }
}

__global__ __launch_bounds__(QTHREADS)
void chamfer_query(int Nq, int Mt, float* __restrict__ out) {
    const int dir = blockIdx.z;             // 0: out->tgt, 1: tgt->out
    const int pair = blockIdx.y;
    const int qlist = (dir ? NPAIRS : 0) + pair;      // own (sorted) set
    const int tlist = (dir ? 0 : NPAIRS) + pair;      // other set
    const int nq = dir ? Mt : Nq;
    const int tn = dir ? Nq : Mt;

    float* sx = s_mem;
    float* sy = s_mem + TSP;
    float* sz = s_mem + 2 * TSP;
    float* sh = s_mem + 3 * TSP;
    unsigned short* sstart = (unsigned short*)(s_mem + 4 * TSP);

    // ---- stage sorted targets as SoA + half-norm; sentinels in pad ----
    for (int j = threadIdx.x; j < TSP; j += QTHREADS) {
        if (j < tn) {
            float4 p = g_sorted[tlist][j];
            sx[j] = p.x; sy[j] = p.y; sz[j] = p.z;
            sh[j] = 0.5f * (p.x * p.x + p.y * p.y + p.z * p.z);
        } else {
            sx[j] = 1e30f; sy[j] = 0.f; sz[j] = 0.f; sh[j] = 3.0e37f;
        }
    }
    for (int c = threadIdx.x; c <= NB; c += QTHREADS)
        sstart[c] = g_start[tlist][c];
    __syncthreads();

    const uint64_t* px = (const uint64_t*)sx;
    const uint64_t* py = (const uint64_t*)sy;
    const uint64_t* pz = (const uint64_t*)sz;
    const uint64_t* ph = (const uint64_t*)sh;

    const int qi = blockIdx.x * QTHREADS + threadIdx.x;
    float lsum = 0.f;
    if (qi < nq) {
        float4 q = g_sorted[qlist][qi];   // sorted queries: warp-coherent
        const float qx = q.x;
        const float q2 = qx * qx + q.y * q.y + q.z * q.z;
        const uint64_t nx = pack2(-qx, -qx);
        const uint64_t ny = pack2(-q.y, -q.y);
        const uint64_t nz = pack2(-q.z, -q.z);
        float mlo = 3.0e37f, mhi = 3.0e37f;

        int qb = min(max(__float2int_rd((qx - GRIDMIN) * INVBW), 0), NB - 1);
        int bl = max(qb - 3, 0);
        int br = min(qb + 4, NB);
        int lo = sstart[bl] & ~1;
        int hi = (sstart[br] + 1) & ~1;
        scan_range(lo, hi, nx, ny, nz, px, py, pz, ph, mlo, mhi);

        // ---- expand until both bin-edge bounds certify exactness ----
        for (int iter = 0; iter < NB; iter++) {
            float best = fmaxf(fmaf(2.0f, fminf(mlo, mhi), q2), 0.0f);
            float lb = fmaxf(qx - (GRIDMIN + bl * BW) - 1e-4f, 0.0f);
            float rb = fmaxf((GRIDMIN + br * BW) - qx - 1e-4f, 0.0f);
            bool dl = (bl == 0) || (lb * lb >= best);
            bool dr = (br == NB) || (rb * rb >= best);
            if (dl && dr) break;
            if (!dl && (dr || lb <= rb)) {
                bl--;
                int na = sstart[bl] & ~1;
                scan_range(na, lo, nx, ny, nz, px, py, pz, ph, mlo, mhi);
                lo = na;
            } else {
                br++;
                int nh = (sstart[br] + 1) & ~1;
                scan_range(hi, nh, nx, ny, nz, px, py, pz, ph, mlo, mhi);
                hi = nh;
            }
        }
        lsum = fmaxf(fmaf(2.0f, fminf(mlo, mhi), q2), 0.0f);
    }

    // ---- block reduce + one atomicAdd ----
#pragma unroll
    for (int off = 16; off; off >>= 1)
        lsum += __shfl_down_sync(0xffffffffu, lsum, off);
    __shared__ float red[QTHREADS / 32];
    const int wid = threadIdx.x >> 5;
    if ((threadIdx.x & 31) == 0) red[wid] = lsum;
    __syncthreads();
    if (threadIdx.x == 0) {
        float tot = 0.f;
#pragma unroll
        for (int w = 0; w < QTHREADS / 32; w++) tot += red[w];
        int b = pair / SDIM;
        int s = pair % SDIM;
        atomicAdd(out + s * BDIM + b, tot / (float)nq);
    }
}

extern "C" void kernel_launch(void* const* d_in, const int* in_sizes, int n_in,
                              void* d_out, int out_size) {
    const float* outp = (const float*)d_in[0];  // [B,S,N,3]
    const float* tgtp = (const float*)d_in[1];  // [B,S,M,3]
    float* out = (float*)d_out;                  // [S,B]

    const int Nq = in_sizes[0] / (NPAIRS * 3);
    const int Mt = in_sizes[1] / (NPAIRS * 3);

    cudaMemsetAsync(out, 0, (size_t)out_size * sizeof(float));

    build_sorted<<<2 * NPAIRS, NB>>>(outp, tgtp, Nq, Mt);

    const size_t smem = (size_t)4 * TSP * sizeof(float) +
                        (NB + 2) * sizeof(unsigned short);
    cudaFuncSetAttribute(chamfer_query,
                         cudaFuncAttributeMaxDynamicSharedMemorySize, (int)smem);

    const int maxq = Nq > Mt ? Nq : Mt;
    dim3 grid((maxq + QTHREADS - 1) / QTHREADS, NPAIRS, 2);
    chamfer_query<<<grid, QTHREADS, smem>>>(Nq, Mt, out);
}

// round 6
// speedup vs baseline: 2.1565x; 1.3702x over previous
#include <cuda_runtime.h>
#include <cstdint>

// Chamfer distance, B=4,S=4 pairs, N=M=4096 Gaussian 3D points.
// Warp-uniform sorted-window exact NN:
//  1) build_sorted: counting-sort each of the 32 lists by x into 256 bins
//     over [-5,5] (edge bins absorb outliers).
//  2) chamfer_query: block stages the sorted target list as SoA
//     (x,y,z,h=0.5*|t|^2) in smem. Each WARP takes 32 sorted (adjacent-x)
//     queries and scans the warp-union bin window with a fully uniform
//     loop (broadcast LDS + packed fma.rn.f32x2, 2 evals / 3 FFMA2).
//     Ballot-driven expansion: if any lane's bin-edge bound fails, the
//     warp extends that side one bin and rescans the new slice. Exact.

#define BDIM 4
#define SDIM 4
#define NPAIRS 16
#define NB 256
#define MAXPTS 4096
#define TSP (MAXPTS + 8)          // padded, even, sentinels at tail
#define GRIDMIN (-5.0f)
#define BW 0.0390625f             /* 10/256 */
#define INVBW 25.6f
#define QTHREADS 256

__device__ float4 g_sorted[2 * NPAIRS][MAXPTS];
__device__ unsigned short g_start[2 * NPAIRS][NB + 1];

__device__ __forceinline__ uint64_t fma2(uint64_t a, uint64_t b, uint64_t c) {
    uint64_t d;
    asm("fma.rn.f32x2 %0, %1, %2, %3;" : "=l"(d) : "l"(a), "l"(b), "l"(c));
    return d;
}
__device__ __forceinline__ uint64_t pack2(float lo, float hi) {
    uint64_t d;
    asm("mov.b64 %0, {%1, %2};" : "=l"(d) : "f"(lo), "f"(hi));
    return d;
}
__device__ __forceinline__ void unpack2(uint64_t v, float& lo, float& hi) {
    asm("mov.b64 {%0, %1}, %2;" : "=f"(lo), "=f"(hi) : "l"(v));
}

// ---------------- counting sort by x into 256 bins ----------------
__global__ void build_sorted(const float* __restrict__ outp,
                             const float* __restrict__ tgtp,
                             int Nq, int Mt) {
    const int list = blockIdx.x;            // 0..31
    const int set = list >> 4, pair = list & 15;
    const float* pts = set ? tgtp : outp;
    const int n = set ? Mt : Nq;
    const float* base = pts + (size_t)pair * n * 3;

    __shared__ int cnt[NB];
    const int t = threadIdx.x;              // 256 threads

    cnt[t] = 0;
    __syncthreads();

    for (int i = t; i < n; i += NB) {
        float x = base[3 * i];
        int b = min(max(__float2int_rd((x - GRIDMIN) * INVBW), 0), NB - 1);
        atomicAdd(&cnt[b], 1);
    }
    __syncthreads();

    int v = cnt[t];
    __syncthreads();
#pragma unroll
    for (int off = 1; off < NB; off <<= 1) {
        int u = (t >= off) ? cnt[t - off] : 0;
        __syncthreads();
        cnt[t] += u;
        __syncthreads();
    }
    int start = cnt[t] - v;  // exclusive

    g_start[list][t] = (unsigned short)start;
    if (t == 0) g_start[list][NB] = (unsigned short)n;

    __syncthreads();
    cnt[t] = start;
    __syncthreads();

    for (int i = t; i < n; i += NB) {
        float x = base[3 * i], y = base[3 * i + 1], z = base[3 * i + 2];
        int b = min(max(__float2int_rd((x - GRIDMIN) * INVBW), 0), NB - 1);
        int idx = atomicAdd(&cnt[b], 1);
        g_sorted[list][idx] = make_float4(x, y, z, 0.f);
    }
}

// ---------------- query ----------------
extern __shared__ float s_mem[];

// warp-uniform scan of even point range [a,b); each lane tracks its own min
__device__ __forceinline__ void scan_range(
    int a, int b,
    uint64_t nx, uint64_t ny, uint64_t nz,
    const uint64_t* __restrict__ px, const uint64_t* __restrict__ py,
    const uint64_t* __restrict__ pz, const uint64_t* __restrict__ ph,
    float& mlo, float& mhi) {
    const int j0 = a >> 1, j1 = b >> 1;
#pragma unroll 4
    for (int j = j0; j < j1; j++) {
        uint64_t t = fma2(nx, px[j], ph[j]);
        t = fma2(ny, py[j], t);
        t = fma2(nz, pz[j], t);
        float lo, hi;
        unpack2(t, lo, hi);
        mlo = fminf(mlo, lo);
        mhi = fminf(mhi, hi);
    }
}

__global__ __launch_bounds__(QTHREADS)
void chamfer_query(int Nq, int Mt, float* __restrict__ out) {
    const int dir = blockIdx.z;             // 0: out->tgt, 1: tgt->out
    const int pair = blockIdx.y;
    const int qlist = (dir ? NPAIRS : 0) + pair;      // own (sorted) set
    const int tlist = (dir ? 0 : NPAIRS) + pair;      // other set
    const int nq = dir ? Mt : Nq;
    const int tn = dir ? Nq : Mt;

    float* sx = s_mem;
    float* sy = s_mem + TSP;
    float* sz = s_mem + 2 * TSP;
    float* sh = s_mem + 3 * TSP;
    unsigned short* sstart = (unsigned short*)(s_mem + 4 * TSP);

    // ---- stage sorted targets as SoA + half-norm; sentinels in pad ----
    for (int j = threadIdx.x; j < TSP; j += QTHREADS) {
        if (j < tn) {
            float4 p = g_sorted[tlist][j];
            sx[j] = p.x; sy[j] = p.y; sz[j] = p.z;
            sh[j] = 0.5f * (p.x * p.x + p.y * p.y + p.z * p.z);
        } else {
            sx[j] = 1e30f; sy[j] = 0.f; sz[j] = 0.f; sh[j] = 3.0e37f;
        }
    }
    for (int c = threadIdx.x; c <= NB; c += QTHREADS)
        sstart[c] = g_start[tlist][c];
    __syncthreads();

    const uint64_t* px = (const uint64_t*)sx;
    const uint64_t* py = (const uint64_t*)sy;
    const uint64_t* pz = (const uint64_t*)sz;
    const uint64_t* ph = (const uint64_t*)sh;

    const int qi = blockIdx.x * QTHREADS + threadIdx.x;
    const bool active = (qi < nq);

    float qx = 0.f, q2 = 0.f;
    uint64_t nx = 0, ny = 0, nz = 0;
    if (active) {
        float4 q = g_sorted[qlist][qi];   // sorted queries: warp-coherent
        qx = q.x;
        q2 = qx * qx + q.y * q.y + q.z * q.z;
        nx = pack2(-qx, -qx);
        ny = pack2(-q.y, -q.y);
        nz = pack2(-q.z, -q.z);
    }
    float mlo = 3.0e37f, mhi = 3.0e37f;

    int qb = min(max(__float2int_rd((qx - GRIDMIN) * INVBW), 0), NB - 1);
    // warp-union window (warp-uniform)
    int BL = qb, BR = qb;
#pragma unroll
    for (int off = 16; off; off >>= 1) {
        BL = min(BL, __shfl_xor_sync(0xffffffffu, BL, off));
        BR = max(BR, __shfl_xor_sync(0xffffffffu, BR, off));
    }
    BL = max(BL - 3, 0);
    BR = min(BR + 4, NB);

    int LO = sstart[BL] & ~1;
    int HI = (sstart[BR] + 1) & ~1;
    scan_range(LO, HI, nx, ny, nz, px, py, pz, ph, mlo, mhi);

    // ---- ballot-driven warp-uniform expansion ----
    for (int iter = 0; iter < NB; iter++) {
        float best = fmaxf(fmaf(2.0f, fminf(mlo, mhi), q2), 0.0f);
        float lb = fmaxf(qx - (GRIDMIN + BL * BW) - 1e-4f, 0.0f);
        float rb = fmaxf((GRIDMIN + BR * BW) - qx - 1e-4f, 0.0f);
        bool needL = active && (BL > 0)  && (lb * lb < best);
        bool needR = active && (BR < NB) && (rb * rb < best);
        unsigned anyL = __ballot_sync(0xffffffffu, needL);
        unsigned anyR = __ballot_sync(0xffffffffu, needR);
        if (!anyL && !anyR) break;
        if (anyL) {
            int nBL = BL - 1;
            int nLO = sstart[nBL] & ~1;
            scan_range(nLO, LO, nx, ny, nz, px, py, pz, ph, mlo, mhi);
            BL = nBL; LO = nLO;
        }
        if (anyR) {
            int nBR = BR + 1;
            int nHI = (sstart[nBR] + 1) & ~1;
            scan_range(HI, nHI, nx, ny, nz, px, py, pz, ph, mlo, mhi);
            BR = nBR; HI = nHI;
        }
    }

    float lsum = active ? fmaxf(fmaf(2.0f, fminf(mlo, mhi), q2), 0.0f) : 0.f;

    // ---- block reduce + one atomicAdd ----
#pragma unroll
    for (int off = 16; off; off >>= 1)
        lsum += __shfl_down_sync(0xffffffffu, lsum, off);
    __shared__ float red[QTHREADS / 32];
    const int wid = threadIdx.x >> 5;
    if ((threadIdx.x & 31) == 0) red[wid] = lsum;
    __syncthreads();
    if (threadIdx.x == 0) {
        float tot = 0.f;
#pragma unroll
        for (int w = 0; w < QTHREADS / 32; w++) tot += red[w];
        int b = pair / SDIM;
        int s = pair % SDIM;
        atomicAdd(out + s * BDIM + b, tot / (float)nq);
    }
}

extern "C" void kernel_launch(void* const* d_in, const int* in_sizes, int n_in,
                              void* d_out, int out_size) {
    const float* outp = (const float*)d_in[0];  // [B,S,N,3]
    const float* tgtp = (const float*)d_in[1];  // [B,S,M,3]
    float* out = (float*)d_out;                  // [S,B]

    const int Nq = in_sizes[0] / (NPAIRS * 3);
    const int Mt = in_sizes[1] / (NPAIRS * 3);

    cudaMemsetAsync(out, 0, (size_t)out_size * sizeof(float));

    build_sorted<<<2 * NPAIRS, NB>>>(outp, tgtp, Nq, Mt);

    const size_t smem = (size_t)4 * TSP * sizeof(float) +
                        (NB + 2) * sizeof(unsigned short);
    cudaFuncSetAttribute(chamfer_query,
                         cudaFuncAttributeMaxDynamicSharedMemorySize, (int)smem);

    const int maxq = Nq > Mt ? Nq : Mt;
    dim3 grid((maxq + QTHREADS - 1) / QTHREADS, NPAIRS, 2);
    chamfer_query<<<grid, QTHREADS, smem>>>(Nq, Mt, out);
}